// round 14
// baseline (speedup 1.0000x reference)
#include <cuda_runtime.h>
#include <math.h>

#define HS   14
#define SEQ  197
#define FULL 0xFFFFFFFFu

// One full masked 8-neighbor byte-min step on 4 packed words (in place).
// Background/pad bytes (nn=0xFF) stay 0xFF; leaked values through background
// h-bytes implement diagonal adjacency exactly (separable 3x3, remasked).
#define MINSTEP(t0, t1, t2, t3)                                              \
    do {                                                                     \
        unsigned sr0 = __funnelshift_r(t0, t1, 8);                           \
        unsigned sr1 = __funnelshift_r(t1, t2, 8);                           \
        unsigned sr2 = __funnelshift_r(t2, t3, 8);                           \
        unsigned sr3 = __funnelshift_r(t3, FULL, 8);                         \
        unsigned sl0 = __funnelshift_l(FULL, t0, 8);                         \
        unsigned sl1 = __funnelshift_l(t0, t1, 8);                           \
        unsigned sl2 = __funnelshift_l(t1, t2, 8);                           \
        unsigned sl3 = __funnelshift_l(t2, t3, 8);                           \
        unsigned h0 = __vminu4(t0, __vminu4(sr0, sl0));                      \
        unsigned h1 = __vminu4(t1, __vminu4(sr1, sl1));                      \
        unsigned h2 = __vminu4(t2, __vminu4(sr2, sl2));                      \
        unsigned h3 = __vminu4(t3, __vminu4(sr3, sl3));                      \
        unsigned u0 = __shfl_up_sync(FULL, h0, 1);                           \
        unsigned d0 = __shfl_down_sync(FULL, h0, 1);                         \
        unsigned u1 = __shfl_up_sync(FULL, h1, 1);                           \
        unsigned d1 = __shfl_down_sync(FULL, h1, 1);                         \
        unsigned u2 = __shfl_up_sync(FULL, h2, 1);                           \
        unsigned d2 = __shfl_down_sync(FULL, h2, 1);                         \
        unsigned u3 = __shfl_up_sync(FULL, h3, 1);                           \
        unsigned d3 = __shfl_down_sync(FULL, h3, 1);                         \
        t0 = __vminu4(h0, __vminu4(u0, d0)) | n0;                            \
        t1 = __vminu4(h1, __vminu4(u1, d1)) | n1;                            \
        t2 = __vminu4(h2, __vminu4(u2, d2)) | n2;                            \
        t3 = __vminu4(h3, __vminu4(u3, d3)) | n3;                            \
    } while (0)

// Two tasks per warp: task A = lanes 0-15, task B = lanes 16-31.
// sub-lane 0..13 owns a grid row; sub 14,15 hold all-0xFF padding rows
// (neutral for byte-min; natural border between the two halves).
__global__ __launch_bounds__(32) void blob_loss_kernel(
    const float* __restrict__ dot_qk,
    float* __restrict__ out,
    float inv_n)
{
    __shared__ unsigned char SLAB[2][512];   // per-task 256B mirrors, slot 255 = 0xFF
    __shared__ float PU[2][224];

    const int lane = threadIdx.x;
    const int sub  = lane & 15;
    const int half = lane >> 4;
    const int task = blockIdx.x * 2 + half;
    const unsigned tofs = (unsigned)(half << 8);

    const bool   rowok = (sub < HS);
    const float* myrow = dot_qk + (size_t)task * (SEQ * SEQ) + 1 + sub * HS;

    ((uint4*)SLAB[0])[lane] = make_uint4(FULL, FULL, FULL, FULL);
    ((uint4*)SLAB[1])[lane] = make_uint4(FULL, FULL, FULL, FULL);
    #pragma unroll
    for (int i = lane; i < 448; i += 32) PU[0][i] = 0.f;

    // ---- load 14 register floats per row-lane; mean per 16-lane half
    float x[HS];
    float rs = 0.f;
    #pragma unroll
    for (int c = 0; c < HS; c++) {
        x[c] = rowok ? myrow[c] : 0.f;
        rs += x[c];
    }
    float s = rs;
    #pragma unroll
    for (int o = 8; o; o >>= 1) s += __shfl_xor_sync(FULL, s, o);
    const float m = s * (1.0f / 196.0f);

    // ---- mask, xv, B
    unsigned mk = 0;
    float xv[HS];
    float b = 0.f;
    #pragma unroll
    for (int c = 0; c < HS; c++) {
        xv[c] = fmaxf(x[c] - m, 0.f) + 1e-9f;
        if (rowok && x[c] > m) { mk |= (1u << c); b += xv[c]; }
    }
    float B = b;
    #pragma unroll
    for (int o = 8; o; o >>= 1) B += __shfl_xor_sync(FULL, B, o);

    // ---- pack initial labels = horizontal RUN-START address (free row closure).
    //      Label <= own address invariant holds. pad lanes: mk=0 -> all 0xFF.
    const unsigned abase = (unsigned)(sub << 4);
    unsigned w0, w1, w2, w3;
    {
        unsigned ww[4];
        unsigned start = 0;
        #pragma unroll
        for (int i = 0; i < 4; i++) {
            unsigned v = 0;
            #pragma unroll
            for (int j = 0; j < 4; j++) {
                int c = 4 * i + j;
                unsigned byte = 0xFFu;
                if (c < HS && ((mk >> c) & 1u)) {
                    if (c == 0 || !((mk >> (c - 1)) & 1u)) start = (unsigned)c;
                    byte = abase + start;
                }
                v |= byte << (8 * j);
            }
            ww[i] = v;
        }
        w0 = ww[0]; w1 = ww[1]; w2 = ww[2]; w3 = ww[3];
    }
    const unsigned n0 = __vcmpeq4(w0 | __vcmpgtu4(w0, w0), w0) & 0u | __vcmpeq4(w0, w0) & 0u | 0u, dummy_n = 0u;
    (void)dummy_n;
    // background byte masks (0xFF where label is 0xFF initially == background/pad)
    #undef  NN_INIT
    const unsigned nA0 = __vcmpeq4(w0, FULL);
    const unsigned nA1 = __vcmpeq4(w1, FULL);
    const unsigned nA2 = __vcmpeq4(w2, FULL);
    const unsigned nA3 = __vcmpeq4(w3, FULL);
    // local names used by MINSTEP
    #define n0 nA0
    #define n1 nA1
    #define n2 nA2
    #define n3 nA3

    // ---- CC: 2 masked min-steps (registers) + double pointer jump per iteration
    int bi = 0;
    for (int it = 0; it < 100; it++) {
        unsigned t0 = w0, t1 = w1, t2 = w2, t3 = w3;
        MINSTEP(t0, t1, t2, t3);
        MINSTEP(t0, t1, t2, t3);

        *(uint4*)&SLAB[bi][tofs + abase] = make_uint4(t0, t1, t2, t3);
        __syncwarp();

        const unsigned char* S = &SLAB[bi][tofs];
        // jump 1
        unsigned a0  = S[t0 & 0xFFu],         a1  = S[(t0 >> 8) & 0xFFu];
        unsigned a2  = S[(t0 >> 16) & 0xFFu], a3  = S[t0 >> 24];
        unsigned a4  = S[t1 & 0xFFu],         a5  = S[(t1 >> 8) & 0xFFu];
        unsigned a6  = S[(t1 >> 16) & 0xFFu], a7  = S[t1 >> 24];
        unsigned a8  = S[t2 & 0xFFu],         a9  = S[(t2 >> 8) & 0xFFu];
        unsigned a10 = S[(t2 >> 16) & 0xFFu], a11 = S[t2 >> 24];
        unsigned a12 = S[t3 & 0xFFu],         a13 = S[(t3 >> 8) & 0xFFu];
        // jump 2 (chain compression squared)
        a0  = S[a0];  a1  = S[a1];  a2  = S[a2];  a3  = S[a3];
        a4  = S[a4];  a5  = S[a5];  a6  = S[a6];  a7  = S[a7];
        a8  = S[a8];  a9  = S[a9];  a10 = S[a10]; a11 = S[a11];
        a12 = S[a12]; a13 = S[a13];

        unsigned g0 = a0  | (a1  << 8) | (a2  << 16) | (a3  << 24);
        unsigned g1 = a4  | (a5  << 8) | (a6  << 16) | (a7  << 24);
        unsigned g2 = a8  | (a9  << 8) | (a10 << 16) | (a11 << 24);
        unsigned g3 = a12 | (a13 << 8) | 0xFFFF0000u;

        // fixpoint test vs iteration-start labels (monotone: g <= t <= w)
        unsigned ch = (g0 ^ w0) | (g1 ^ w1) | (g2 ^ w2) | (g3 ^ w3);
        w0 = g0; w1 = g1; w2 = g2; w3 = g3;
        bi ^= 1;
        if (!__any_sync(FULL, ch != 0u)) break;
    }
    #undef n0
    #undef n1
    #undef n2
    #undef n3

    // ---- per-component sums (task-local padded addresses)
    __syncwarp();
    float* PUt = PU[half];
    if (rowok) {
        #pragma unroll
        for (int c = 0; c < HS; c++) {
            if ((mk >> c) & 1u) {
                unsigned lb;
                if      (c < 4)  lb = (w0 >> (8 * c))        & 0xFFu;
                else if (c < 8)  lb = (w1 >> (8 * (c - 4)))  & 0xFFu;
                else if (c < 12) lb = (w2 >> (8 * (c - 8)))  & 0xFFu;
                else             lb = (w3 >> (8 * (c - 12))) & 0xFFu;
                atomicAdd(&PUt[lb], xv[c]);
            }
        }
    }
    __syncwarp();

    // ---- entropy at roots (label == own padded address), reduce per half
    float h = 0.f;
    const float invB = 1.0f / B;
    if (rowok) {
        #pragma unroll
        for (int c = 0; c < HS; c++) {
            if ((mk >> c) & 1u) {
                unsigned lb;
                if      (c < 4)  lb = (w0 >> (8 * c))        & 0xFFu;
                else if (c < 8)  lb = (w1 >> (8 * (c - 4)))  & 0xFFu;
                else if (c < 12) lb = (w2 >> (8 * (c - 8)))  & 0xFFu;
                else             lb = (w3 >> (8 * (c - 12))) & 0xFFu;
                if (lb == abase + c) {
                    float pn = PUt[lb] * invB;
                    h -= pn * __logf(pn);
                }
            }
        }
    }
    #pragma unroll
    for (int o = 8; o; o >>= 1) h += __shfl_xor_sync(FULL, h, o);
    if (sub == 0) atomicAdd(out, h * inv_n);
}

extern "C" void kernel_launch(void* const* d_in, const int* in_sizes, int n_in,
                              void* d_out, int out_size)
{
    const float* dq = (const float*)d_in[0];
    float* out = (float*)d_out;
    const int n = in_sizes[0] / (SEQ * SEQ);   // 128*12 = 1536 (even)

    cudaMemsetAsync(out, 0, sizeof(float));
    blob_loss_kernel<<<n / 2, 32>>>(dq, out, 1.0f / (float)n);
}